// round 9
// baseline (speedup 1.0000x reference)
#include <cuda_runtime.h>
#include <math_constants.h>
#include <cstdint>

#define BATCH 64
#define LSEQ  900
#define DHEAD 64
#define TQ    32          // query rows per CTA
#define TKB   256         // key/value cols per chunk (phase B & C)
#define SPITCH 960        // padded score row pitch
#define NTHREADS 512

typedef unsigned long long ull;

// Per-batch V column sums (device-global scratch; no allocation).
__device__ __align__(16) float g_full[BATCH * DHEAD];
__device__ __align__(16) float g_tail[BATCH * DHEAD];

__device__ __forceinline__ void cp_async16(uint32_t dsm, const void* src, int szbytes) {
    asm volatile("cp.async.cg.shared.global [%0], [%1], 16, %2;\n"
                 :: "r"(dsm), "l"(src), "r"(szbytes));
}
__device__ __forceinline__ ull pack2(float a, float b) {
    ull r; asm("mov.b64 %0, {%1, %2};" : "=l"(r) : "f"(a), "f"(b)); return r;
}
__device__ __forceinline__ float2 unpack2(ull v) {
    float2 r; asm("mov.b64 {%0, %1}, %2;" : "=f"(r.x), "=f"(r.y) : "l"(v)); return r;
}
__device__ __forceinline__ ull fma2(ull a, ull b, ull c) {
    ull d; asm("fma.rn.f32x2 %0, %1, %2, %3;" : "=l"(d) : "l"(a), "l"(b), "l"(c)); return d;
}

// ---------------- kernel 1: per-batch full & tail V sums ----------------
__global__ void vsum_kernel(const float* __restrict__ V, const int* __restrict__ dur)
{
    __shared__ float sf[4][64];
    __shared__ float st_[4][64];
    const int b   = blockIdx.x;
    const int d   = threadIdx.x & 63;
    const int seg = threadIdx.x >> 6;
    const int durb = dur[b];
    const float* vb = V + (size_t)b * LSEQ * DHEAD;
    const int c0 = seg * 225, c1 = c0 + 225;
    float full = 0.f, tail = 0.f;
    for (int c = c0; c < c1; c++) {
        float v = vb[(size_t)c * DHEAD + d];
        full += v;
        if (c >= durb) tail += v;
    }
    sf[seg][d] = full;  st_[seg][d] = tail;
    __syncthreads();
    if (seg == 0) {
        g_full[b * 64 + d] = sf[0][d] + sf[1][d] + sf[2][d] + sf[3][d];
        g_tail[b * 64 + d] = st_[0][d] + st_[1][d] + st_[2][d] + st_[3][d];
    }
}

// ---------------- kernel 2: fused masked attention ----------------------
// SMEM floats: S 30720 | Qs2 4096 (dup pairs, ull[64*32]) | Ks 16384 | pm 32 | uf 32
#define SMEM_FLOATS (TQ * SPITCH + 4096 + 16384 + 64)

__global__ __launch_bounds__(NTHREADS, 1)
void sdpa_fused_kernel(const float* __restrict__ Q,
                       const float* __restrict__ K,
                       const float* __restrict__ V,
                       const int*   __restrict__ dur,
                       float* __restrict__ out,
                       float* __restrict__ score)
{
    extern __shared__ float sm[];
    float* S    = sm;                       // [TQ][SPITCH]
    ull*   Qs2  = (ull*)(sm + TQ * SPITCH); // dup Q pairs: Qs2[d*32 + qi] = {q,q}
    float* Ks   = sm + TQ * SPITCH + 4096;  // swizzled transposed K / natural V
    float* pmv  = Ks + 16384;               // per-row masked prob
    float* ufv  = pmv + 32;                 // per-row uniform value

    const int tid  = threadIdx.x;
    const int b    = blockIdx.y;
    const int q0   = blockIdx.x * TQ;
    const int durb = dur[b];
    const int warp = tid >> 5;
    const int lane = tid & 31;
    const float inv900 = 1.0f / 900.0f;

    // ---- fast path: whole tile fully masked -> uniform rows --------------
    if (q0 >= durb) {
        const float4 u4 = make_float4(inv900, inv900, inv900, inv900);
        for (int qi = warp; qi < TQ; qi += 16) {
            int r = q0 + qi;
            if (r < LSEQ) {
                float* srow = score + ((size_t)b * LSEQ + r) * LSEQ;
                for (int g = lane; g < 225; g += 32)
                    __stcs((float4*)&srow[4 * g], u4);
            }
        }
        for (int e = tid; e < TQ * DHEAD; e += NTHREADS) {
            int qi = e >> 6, d = e & 63, r = q0 + qi;
            if (r < LSEQ)
                out[((size_t)b * LSEQ + r) * DHEAD + d] = g_full[b * 64 + d] * inv900;
        }
        return;
    }

    const int CP  = (durb + 63) & ~63;         // padded valid-col count (<=960)
    const int nch = (CP + TKB - 1) / TKB;

    const float* qb = Q + (size_t)b * LSEQ * DHEAD;
    const float* kb = K + (size_t)b * LSEQ * DHEAD;
    const float* vb = V + (size_t)b * LSEQ * DHEAD;

    // ---- Phase A: Q tile transposed + duplicated into SMEM ---------------
    for (int e = tid; e < TQ * DHEAD; e += NTHREADS) {
        int qi = e >> 6, d = e & 63, r = q0 + qi;
        float q = (r < durb) ? qb[(size_t)r * DHEAD + d] : 0.0f;
        Qs2[d * 32 + qi] = pack2(q, q);
    }

    const int qg = tid >> 6;      // 0..7  -> rows {4qg..4qg+3}
    const int cg = tid & 63;      // 0..63 -> cols {4cg..4cg+3} within chunk

    // ---- Phase B: S = (Q K^T)/8 over valid columns only ------------------
    for (int ck = 0; ck < nch; ck++) {
        const int c0    = ck * TKB;
        const int width = min(TKB, CP - c0);
        __syncthreads();
        // K chunk -> swizzled transposed SMEM
        #pragma unroll
        for (int it = 0; it < 8; it++) {
            int vidx = tid + NTHREADS * it;
            int kj = vidx >> 4;
            int d4 = (vidx & 15) << 2;
            if (kj < width) {
                int c = c0 + kj;
                float4 kv = make_float4(0.f, 0.f, 0.f, 0.f);
                if (c < durb) kv = *(const float4*)&kb[(size_t)c * DHEAD + d4];
                const float* kvp = (const float*)&kv;
                #pragma unroll
                for (int u = 0; u < 4; u++) {
                    int d = d4 + u;
                    int g = (kj >> 2) ^ ((d >> 2) & 15);
                    Ks[(d << 8) + (g << 2) + (kj & 3)] = kvp[u];
                }
            }
        }
        __syncthreads();

        if (4 * cg < width) {
            ull a2[4][2];
            #pragma unroll
            for (int i = 0; i < 4; i++) { a2[i][0] = 0ull; a2[i][1] = 0ull; }

            const ull* qp = Qs2 + 4 * qg;
            #pragma unroll 8
            for (int d = 0; d < DHEAD; d++) {
                ulonglong2 qa = *(const ulonglong2*)(qp + d * 32);       // rows 0,1
                ulonglong2 qb2 = *(const ulonglong2*)(qp + d * 32 + 2);  // rows 2,3
                ulonglong2 kk = *(const ulonglong2*)&Ks[(d << 8) + ((cg ^ ((d >> 2) & 15)) << 2)];
                a2[0][0] = fma2(qa.x,  kk.x, a2[0][0]);  a2[0][1] = fma2(qa.x,  kk.y, a2[0][1]);
                a2[1][0] = fma2(qa.y,  kk.x, a2[1][0]);  a2[1][1] = fma2(qa.y,  kk.y, a2[1][1]);
                a2[2][0] = fma2(qb2.x, kk.x, a2[2][0]);  a2[2][1] = fma2(qb2.x, kk.y, a2[2][1]);
                a2[3][0] = fma2(qb2.y, kk.x, a2[3][0]);  a2[3][1] = fma2(qb2.y, kk.y, a2[3][1]);
            }

            const int cbase = c0 + 4 * cg;
            const float scl = 0.125f;
            #pragma unroll
            for (int i = 0; i < 4; i++) {
                float2 p0 = unpack2(a2[i][0]);
                float2 p1 = unpack2(a2[i][1]);
                float accv[4] = {p0.x, p0.y, p1.x, p1.y};
                float4 sv;
                float* svp = (float*)&sv;
                #pragma unroll
                for (int j = 0; j < 4; j++) {
                    int c = cbase + j;
                    svp[j] = (c < durb) ? accv[j] * scl : -CUDART_INF_F;
                }
                *(float4*)&S[(4 * qg + i) * SPITCH + cbase] = sv;
            }
        }
    }
    __syncthreads();

    // ---- Softmax per row (float4) + analytic masked tail + score write ---
    {
        const int NG = CP >> 2;          // float4 groups in valid region
        for (int qi = warp; qi < TQ; qi += 16) {
            const int r = q0 + qi;
            float* row = &S[qi * SPITCH];
            if (r < durb) {
                float m = -CUDART_INF_F;
                for (int g = lane; g < NG; g += 32) {
                    float4 v = *(const float4*)&row[4 * g];
                    m = fmaxf(m, fmaxf(fmaxf(v.x, v.y), fmaxf(v.z, v.w)));
                }
                #pragma unroll
                for (int o = 16; o; o >>= 1) m = fmaxf(m, __shfl_xor_sync(0xffffffffu, m, o));
                if (durb < LSEQ) m = fmaxf(m, -1e-12f);

                float ssum = 0.0f;
                for (int g = lane; g < NG; g += 32) {
                    float4 v = *(const float4*)&row[4 * g];
                    v.x = __expf(v.x - m);  v.y = __expf(v.y - m);
                    v.z = __expf(v.z - m);  v.w = __expf(v.w - m);
                    *(float4*)&row[4 * g] = v;
                    ssum += (v.x + v.y) + (v.z + v.w);
                }
                #pragma unroll
                for (int o = 16; o; o >>= 1) ssum += __shfl_xor_sync(0xffffffffu, ssum, o);

                float e_mask = (durb < LSEQ) ? __expf(-1e-12f - m) : 0.0f;
                float Z   = ssum + (float)(LSEQ - durb) * e_mask;
                float inv = 1.0f / Z;
                float pmask = e_mask * inv;
                if (lane == 0) { pmv[qi] = pmask; ufv[qi] = 0.0f; }

                float* srow = score + ((size_t)b * LSEQ + r) * LSEQ;
                for (int g = lane; g < 225; g += 32) {
                    int c = 4 * g;
                    float4 rv = *(const float4*)&row[c];   // garbage beyond CP, unused
                    float4 ov, wv;
                    float* rp = (float*)&rv; float* op = (float*)&ov; float* wp = (float*)&wv;
                    #pragma unroll
                    for (int u = 0; u < 4; u++) {
                        bool vld = (c + u) < durb;
                        float p = rp[u] * inv;
                        op[u] = vld ? p : pmask;
                        wp[u] = vld ? p : 0.0f;
                    }
                    if (c < CP) *(float4*)&row[c] = wv;
                    __stcs((float4*)&srow[c], ov);
                }
            } else {
                const float4 z4 = make_float4(0.f, 0.f, 0.f, 0.f);
                for (int g = lane; g < NG; g += 32) *(float4*)&row[4 * g] = z4;
                if (lane == 0) { pmv[qi] = 0.0f; ufv[qi] = inv900; }
                if (r < LSEQ) {
                    const float4 u4 = make_float4(inv900, inv900, inv900, inv900);
                    float* srow = score + ((size_t)b * LSEQ + r) * LSEQ;
                    for (int g = lane; g < 225; g += 32)
                        __stcs((float4*)&srow[4 * g], u4);
                }
            }
        }
    }
    __syncthreads();

    // ---- Phase C: out = P(valid) @ V + pmask*Tail + uniform*Full ---------
    {
        const int qg2 = tid >> 6;        // 0..7  -> rows {4qg2..4qg2+3}
        const int dg  = tid & 15;        // 0..15 -> out cols {4dg..4dg+3}
        const int rep = (tid >> 4) & 3;  // split-K x4
        float* Vs = Ks;                  // natural layout [cc][64]

        ull c2[4][2];
        #pragma unroll
        for (int i = 0; i < 4; i++) { c2[i][0] = 0ull; c2[i][1] = 0ull; }

        for (int ck = 0; ck < nch; ck++) {
            const int c0   = ck * TKB;
            const int clen = min(TKB, CP - c0);
            __syncthreads();
            #pragma unroll
            for (int it = 0; it < 8; it++) {
                int vidx = tid + NTHREADS * it;
                int cc = vidx >> 4;
                int d4 = (vidx & 15) << 2;
                if (cc < clen) {
                    int c = c0 + cc;
                    uint32_t dsm = (uint32_t)__cvta_generic_to_shared(&Vs[cc * 64 + d4]);
                    const float* src = (c < durb) ? &vb[(size_t)c * DHEAD + d4] : vb;
                    cp_async16(dsm, src, (c < durb) ? 16 : 0);
                }
            }
            asm volatile("cp.async.commit_group;\n" ::: "memory");
            asm volatile("cp.async.wait_group 0;\n" ::: "memory");
            __syncthreads();

            const int ngr = clen >> 2;
            #pragma unroll 2
            for (int ccg = rep; ccg < ngr; ccg += 4) {
                const int cb = c0 + 4 * ccg;
                float4 p[4];
                #pragma unroll
                for (int i = 0; i < 4; i++)
                    p[i] = *(const float4*)&S[(4 * qg2 + i) * SPITCH + cb];
                #pragma unroll
                for (int u = 0; u < 4; u++) {
                    ulonglong2 vv = *(const ulonglong2*)&Vs[(4 * ccg + u) * 64 + 4 * dg];
                    #pragma unroll
                    for (int i = 0; i < 4; i++) {
                        float pu = ((const float*)&p[i])[u];
                        ull pu2 = pack2(pu, pu);
                        c2[i][0] = fma2(pu2, vv.x, c2[i][0]);
                        c2[i][1] = fma2(pu2, vv.y, c2[i][1]);
                    }
                }
            }
        }

        // unpack packed accumulators
        float acc[4][4];
        #pragma unroll
        for (int i = 0; i < 4; i++) {
            float2 lo = unpack2(c2[i][0]);
            float2 hi = unpack2(c2[i][1]);
            acc[i][0] = lo.x; acc[i][1] = lo.y; acc[i][2] = hi.x; acc[i][3] = hi.y;
        }
        __syncthreads();

        // split-K reduction in SMEM (reuse Qs2/Ks region), padded stride 20
        float* red = (float*)Qs2;
        const int cell = (qg2 * 16 + dg) * 20;
        if (rep) {
            #pragma unroll
            for (int i = 0; i < 4; i++)
                *(float4*)&red[(rep - 1) * 2560 + cell + 4 * i] =
                    make_float4(acc[i][0], acc[i][1], acc[i][2], acc[i][3]);
        }
        __syncthreads();
        if (rep == 0) {
            #pragma unroll
            for (int s = 0; s < 3; s++)
                #pragma unroll
                for (int i = 0; i < 4; i++) {
                    float4 rv = *(const float4*)&red[s * 2560 + cell + 4 * i];
                    acc[i][0] += rv.x;  acc[i][1] += rv.y;
                    acc[i][2] += rv.z;  acc[i][3] += rv.w;
                }
            float4 tl = *(const float4*)&g_tail[b * 64 + 4 * dg];
            float4 fl = *(const float4*)&g_full[b * 64 + 4 * dg];
            #pragma unroll
            for (int i = 0; i < 4; i++) {
                int qi = 4 * qg2 + i;
                int r  = q0 + qi;
                if (r < LSEQ) {
                    float pm = pmv[qi], uf = ufv[qi];
                    float4 ov;
                    ov.x = acc[i][0] + pm * tl.x + uf * fl.x;
                    ov.y = acc[i][1] + pm * tl.y + uf * fl.y;
                    ov.z = acc[i][2] + pm * tl.z + uf * fl.z;
                    ov.w = acc[i][3] + pm * tl.w + uf * fl.w;
                    *(float4*)&out[((size_t)b * LSEQ + r) * DHEAD + 4 * dg] = ov;
                }
            }
        }
    }
}

extern "C" void kernel_launch(void* const* d_in, const int* in_sizes, int n_in,
                              void* d_out, int out_size)
{
    (void)in_sizes; (void)n_in; (void)out_size;
    const float* Q   = (const float*)d_in[0];
    const float* K   = (const float*)d_in[1];
    const float* V   = (const float*)d_in[2];
    const int*   dur = (const int*)d_in[3];

    float* out   = (float*)d_out;
    float* score = out + (size_t)BATCH * LSEQ * DHEAD;   // tuple order: (out, score)

    vsum_kernel<<<BATCH, 256>>>(V, dur);

    const int smem_bytes = SMEM_FLOATS * (int)sizeof(float);   // 205,056 B
    cudaFuncSetAttribute(sdpa_fused_kernel,
                         cudaFuncAttributeMaxDynamicSharedMemorySize, smem_bytes);
    dim3 grid((LSEQ + TQ - 1) / TQ, BATCH);   // (29, 64)
    sdpa_fused_kernel<<<grid, NTHREADS, smem_bytes>>>(Q, K, V, dur, out, score);
}

// round 11
// speedup vs baseline: 1.1365x; 1.1365x over previous
#include <cuda_runtime.h>
#include <math_constants.h>
#include <cstdint>

#define BATCH 64
#define LSEQ  900
#define DHEAD 64
#define TQ    32          // query rows per CTA
#define TKB   256         // key cols per chunk (phase B)
#define TKC   128         // value cols per sub-chunk (phase C, double-buffered)
#define SPITCH 960        // padded score row pitch
#define QPITCH 36
#define NTHREADS 512

// Per-batch V column sums (device-global scratch; no allocation).
__device__ __align__(16) float g_full[BATCH * DHEAD];
__device__ __align__(16) float g_tail[BATCH * DHEAD];

__device__ __forceinline__ void cp_async16(uint32_t dsm, const void* src, int szbytes) {
    asm volatile("cp.async.cg.shared.global [%0], [%1], 16, %2;\n"
                 :: "r"(dsm), "l"(src), "r"(szbytes));
}

// ---------------- kernel 1: per-batch full & tail V sums ----------------
__global__ void vsum_kernel(const float* __restrict__ V, const int* __restrict__ dur)
{
    __shared__ float sf[4][64];
    __shared__ float st_[4][64];
    const int b   = blockIdx.x;
    const int d   = threadIdx.x & 63;
    const int seg = threadIdx.x >> 6;
    const int durb = dur[b];
    const float* vb = V + (size_t)b * LSEQ * DHEAD;
    const int c0 = seg * 225, c1 = c0 + 225;
    float full = 0.f, tail = 0.f;
    for (int c = c0; c < c1; c++) {
        float v = vb[(size_t)c * DHEAD + d];
        full += v;
        if (c >= durb) tail += v;
    }
    sf[seg][d] = full;  st_[seg][d] = tail;
    __syncthreads();
    if (seg == 0) {
        g_full[b * 64 + d] = sf[0][d] + sf[1][d] + sf[2][d] + sf[3][d];
        g_tail[b * 64 + d] = st_[0][d] + st_[1][d] + st_[2][d] + st_[3][d];
    }
}

// ---------------- kernel 2: fused masked attention ----------------------
// SMEM floats: S 30720 | Qs 2304 (pitch 36, transposed) | Ks 16384 (K swizzled / 2x V halves / red) | pm 32 | uf 32
#define SMEM_FLOATS (TQ * SPITCH + 2304 + 16384 + 64)

__global__ __launch_bounds__(NTHREADS, 1)
void sdpa_fused_kernel(const float* __restrict__ Q,
                       const float* __restrict__ K,
                       const float* __restrict__ V,
                       const int*   __restrict__ dur,
                       float* __restrict__ out,
                       float* __restrict__ score)
{
    extern __shared__ float sm[];
    float* S   = sm;                       // [TQ][SPITCH]
    float* Qs  = sm + TQ * SPITCH;         // transposed Q: Qs[d*36 + qi]
    float* Ks  = Qs + 2304;                // swizzled transposed K / 2x V half-buffers
    float* pmv = Ks + 16384;               // per-row masked prob
    float* ufv = pmv + 32;                 // per-row uniform value

    const int tid  = threadIdx.x;
    const int b    = blockIdx.y;
    const int q0   = blockIdx.x * TQ;
    const int durb = dur[b];
    const int warp = tid >> 5;
    const int lane = tid & 31;
    const float inv900 = 1.0f / 900.0f;

    // ---- fast path: whole tile fully masked -> uniform rows --------------
    if (q0 >= durb) {
        const float4 u4 = make_float4(inv900, inv900, inv900, inv900);
        for (int qi = warp; qi < TQ; qi += 16) {
            int r = q0 + qi;
            if (r < LSEQ) {
                float* srow = score + ((size_t)b * LSEQ + r) * LSEQ;
                for (int g = lane; g < 225; g += 32)
                    __stcs((float4*)&srow[4 * g], u4);
            }
        }
        for (int e = tid; e < TQ * DHEAD; e += NTHREADS) {
            int qi = e >> 6, d = e & 63, r = q0 + qi;
            if (r < LSEQ)
                out[((size_t)b * LSEQ + r) * DHEAD + d] = g_full[b * 64 + d] * inv900;
        }
        return;
    }

    const int CP  = (durb + 63) & ~63;         // padded valid-col count (<=960)
    const int nch = (CP + TKB - 1) / TKB;

    const float* qb = Q + (size_t)b * LSEQ * DHEAD;
    const float* kb = K + (size_t)b * LSEQ * DHEAD;
    const float* vb = V + (size_t)b * LSEQ * DHEAD;

    // ---- Phase A: Q tile transposed into SMEM ----------------------------
    for (int e = tid; e < TQ * DHEAD; e += NTHREADS) {
        int qi = e >> 6, d = e & 63, r = q0 + qi;
        Qs[d * QPITCH + qi] = (r < durb) ? qb[(size_t)r * DHEAD + d] : 0.0f;
    }

    const int qg = tid >> 6;      // 0..7  -> rows {4qg..4qg+3}
    const int cg = tid & 63;      // 0..63 -> cols {4cg..4cg+3} within chunk

    // ---- Phase B: S = (Q K^T)/8 over valid columns only ------------------
    for (int ck = 0; ck < nch; ck++) {
        const int c0    = ck * TKB;
        const int width = min(TKB, CP - c0);
        __syncthreads();
        // K chunk -> swizzled transposed SMEM; LDGs batched in groups of 4 (MLP)
        #pragma unroll
        for (int grp = 0; grp < 2; grp++) {
            float4 stage[4];
            #pragma unroll
            for (int it = 0; it < 4; it++) {
                int vidx = tid + NTHREADS * (grp * 4 + it);
                int kj = vidx >> 4;
                int d4 = (vidx & 15) << 2;
                int c  = c0 + kj;
                stage[it] = make_float4(0.f, 0.f, 0.f, 0.f);
                if (kj < width && c < durb)
                    stage[it] = *(const float4*)&kb[(size_t)c * DHEAD + d4];
            }
            #pragma unroll
            for (int it = 0; it < 4; it++) {
                int vidx = tid + NTHREADS * (grp * 4 + it);
                int kj = vidx >> 4;
                int d4 = (vidx & 15) << 2;
                if (kj < width) {
                    const float* sp = (const float*)&stage[it];
                    #pragma unroll
                    for (int u = 0; u < 4; u++) {
                        int d = d4 + u;
                        int g = (kj >> 2) ^ ((d >> 2) & 15);
                        Ks[(d << 8) + (g << 2) + (kj & 3)] = sp[u];
                    }
                }
            }
        }
        __syncthreads();

        if (4 * cg < width) {
            float acc[4][4];
            #pragma unroll
            for (int i = 0; i < 4; i++)
                #pragma unroll
                for (int j = 0; j < 4; j++) acc[i][j] = 0.f;

            const float* qp = Qs + 4 * qg;
            #pragma unroll 8
            for (int d = 0; d < DHEAD; d++) {
                float4 qv = *(const float4*)&qp[d * QPITCH];
                float4 kv = *(const float4*)&Ks[(d << 8) + ((cg ^ ((d >> 2) & 15)) << 2)];
                const float* qf = (const float*)&qv;
                #pragma unroll
                for (int i = 0; i < 4; i++) {
                    acc[i][0] += qf[i] * kv.x;  acc[i][1] += qf[i] * kv.y;
                    acc[i][2] += qf[i] * kv.z;  acc[i][3] += qf[i] * kv.w;
                }
            }

            const int cbase = c0 + 4 * cg;
            const float scl = 0.125f;
            #pragma unroll
            for (int i = 0; i < 4; i++) {
                float4 sv;
                float* svp = (float*)&sv;
                #pragma unroll
                for (int j = 0; j < 4; j++) {
                    int c = cbase + j;
                    svp[j] = (c < durb) ? acc[i][j] * scl : -CUDART_INF_F;
                }
                *(float4*)&S[(4 * qg + i) * SPITCH + cbase] = sv;
            }
        }
    }
    __syncthreads();

    // ---- Softmax per row (float4) + analytic masked tail + score write ---
    {
        const int NG = CP >> 2;          // float4 groups in valid region
        for (int qi = warp; qi < TQ; qi += 16) {
            const int r = q0 + qi;
            float* row = &S[qi * SPITCH];
            if (r < durb) {
                float m = -CUDART_INF_F;
                for (int g = lane; g < NG; g += 32) {
                    float4 v = *(const float4*)&row[4 * g];
                    m = fmaxf(m, fmaxf(fmaxf(v.x, v.y), fmaxf(v.z, v.w)));
                }
                #pragma unroll
                for (int o = 16; o; o >>= 1) m = fmaxf(m, __shfl_xor_sync(0xffffffffu, m, o));
                if (durb < LSEQ) m = fmaxf(m, -1e-12f);

                float ssum = 0.0f;
                for (int g = lane; g < NG; g += 32) {
                    float4 v = *(const float4*)&row[4 * g];
                    v.x = __expf(v.x - m);  v.y = __expf(v.y - m);
                    v.z = __expf(v.z - m);  v.w = __expf(v.w - m);
                    *(float4*)&row[4 * g] = v;
                    ssum += (v.x + v.y) + (v.z + v.w);
                }
                #pragma unroll
                for (int o = 16; o; o >>= 1) ssum += __shfl_xor_sync(0xffffffffu, ssum, o);

                float e_mask = (durb < LSEQ) ? __expf(-1e-12f - m) : 0.0f;
                float Z   = ssum + (float)(LSEQ - durb) * e_mask;
                float inv = 1.0f / Z;
                float pmask = e_mask * inv;
                if (lane == 0) { pmv[qi] = pmask; ufv[qi] = 0.0f; }

                float* srow = score + ((size_t)b * LSEQ + r) * LSEQ;
                for (int g = lane; g < 225; g += 32) {
                    int c = 4 * g;
                    float4 rv = *(const float4*)&row[c];   // garbage beyond CP, unused
                    float4 ov, wv;
                    float* rp = (float*)&rv; float* op = (float*)&ov; float* wp = (float*)&wv;
                    #pragma unroll
                    for (int u = 0; u < 4; u++) {
                        bool vld = (c + u) < durb;
                        float p = rp[u] * inv;
                        op[u] = vld ? p : pmask;
                        wp[u] = vld ? p : 0.0f;
                    }
                    if (c < CP) *(float4*)&row[c] = wv;
                    __stcs((float4*)&srow[c], ov);
                }
            } else {
                const float4 z4 = make_float4(0.f, 0.f, 0.f, 0.f);
                for (int g = lane; g < NG; g += 32) *(float4*)&row[4 * g] = z4;
                if (lane == 0) { pmv[qi] = 0.0f; ufv[qi] = inv900; }
                if (r < LSEQ) {
                    const float4 u4 = make_float4(inv900, inv900, inv900, inv900);
                    float* srow = score + ((size_t)b * LSEQ + r) * LSEQ;
                    for (int g = lane; g < 225; g += 32)
                        __stcs((float4*)&srow[4 * g], u4);
                }
            }
        }
    }
    __syncthreads();

    // ---- Phase C: out = P(valid) @ V, double-buffered cp.async V ---------
    {
        const int qg2 = tid >> 6;        // 0..7  -> rows {4qg2..4qg2+3}
        const int dg  = tid & 15;        // 0..15 -> out cols {4dg..4dg+3}
        const int rep = (tid >> 4) & 3;  // split-K x4
        float* Vs = Ks;                  // two halves of 8192 floats each

        float acc[4][4];
        #pragma unroll
        for (int i = 0; i < 4; i++)
            #pragma unroll
            for (int j = 0; j < 4; j++) acc[i][j] = 0.f;

        const int nck = (CP + TKC - 1) / TKC;   // 128-col sub-chunks (<=8)

        // prefetch sub-chunk 0 into half 0
        {
            const int clen0 = min(TKC, CP);
            #pragma unroll
            for (int it = 0; it < 4; it++) {
                int idx = tid + NTHREADS * it;
                int cc = idx >> 4, d4 = (idx & 15) << 2;
                if (cc < clen0) {
                    int c = cc;
                    uint32_t dsm = (uint32_t)__cvta_generic_to_shared(&Vs[cc * 64 + d4]);
                    const float* src = (c < durb) ? &vb[(size_t)c * DHEAD + d4] : vb;
                    cp_async16(dsm, src, (c < durb) ? 16 : 0);
                }
            }
            asm volatile("cp.async.commit_group;\n" ::: "memory");
        }

        for (int ci = 0; ci < nck; ci++) {
            const int buf0 = (ci & 1) * 8192;
            const int c0   = ci * TKC;
            const int clen = min(TKC, CP - c0);

            if (ci + 1 < nck) {
                const int c0n   = (ci + 1) * TKC;
                const int clen2 = min(TKC, CP - c0n);
                const int bufn  = ((ci + 1) & 1) * 8192;
                #pragma unroll
                for (int it = 0; it < 4; it++) {
                    int idx = tid + NTHREADS * it;
                    int cc = idx >> 4, d4 = (idx & 15) << 2;
                    if (cc < clen2) {
                        int c = c0n + cc;
                        uint32_t dsm = (uint32_t)__cvta_generic_to_shared(&Vs[bufn + cc * 64 + d4]);
                        const float* src = (c < durb) ? &vb[(size_t)c * DHEAD + d4] : vb;
                        cp_async16(dsm, src, (c < durb) ? 16 : 0);
                    }
                }
                asm volatile("cp.async.commit_group;\n" ::: "memory");
                asm volatile("cp.async.wait_group 1;\n" ::: "memory");
            } else {
                asm volatile("cp.async.wait_group 0;\n" ::: "memory");
            }
            __syncthreads();

            const int ngr = clen >> 2;
            #pragma unroll 2
            for (int ccg = rep; ccg < ngr; ccg += 4) {
                const int cb = c0 + 4 * ccg;
                float4 p[4];
                #pragma unroll
                for (int i = 0; i < 4; i++)
                    p[i] = *(const float4*)&S[(4 * qg2 + i) * SPITCH + cb];
                #pragma unroll
                for (int u = 0; u < 4; u++) {
                    float4 vv = *(const float4*)&Vs[buf0 + (4 * ccg + u) * 64 + 4 * dg];
                    #pragma unroll
                    for (int i = 0; i < 4; i++) {
                        float pu = ((const float*)&p[i])[u];
                        acc[i][0] += pu * vv.x;  acc[i][1] += pu * vv.y;
                        acc[i][2] += pu * vv.z;  acc[i][3] += pu * vv.w;
                    }
                }
            }
            __syncthreads();
        }

        // split-K reduction in SMEM (reuse Qs/Ks region), padded stride 20
        float* red = Qs;
        const int cell = (qg2 * 16 + dg) * 20;
        if (rep) {
            #pragma unroll
            for (int i = 0; i < 4; i++)
                *(float4*)&red[(rep - 1) * 2560 + cell + 4 * i] =
                    make_float4(acc[i][0], acc[i][1], acc[i][2], acc[i][3]);
        }
        __syncthreads();
        if (rep == 0) {
            #pragma unroll
            for (int s = 0; s < 3; s++)
                #pragma unroll
                for (int i = 0; i < 4; i++) {
                    float4 rv = *(const float4*)&red[s * 2560 + cell + 4 * i];
                    acc[i][0] += rv.x;  acc[i][1] += rv.y;
                    acc[i][2] += rv.z;  acc[i][3] += rv.w;
                }
            float4 tl = *(const float4*)&g_tail[b * 64 + 4 * dg];
            float4 fl = *(const float4*)&g_full[b * 64 + 4 * dg];
            #pragma unroll
            for (int i = 0; i < 4; i++) {
                int qi = 4 * qg2 + i;
                int r  = q0 + qi;
                if (r < LSEQ) {
                    float pm = pmv[qi], uf = ufv[qi];
                    float4 ov;
                    ov.x = acc[i][0] + pm * tl.x + uf * fl.x;
                    ov.y = acc[i][1] + pm * tl.y + uf * fl.y;
                    ov.z = acc[i][2] + pm * tl.z + uf * fl.z;
                    ov.w = acc[i][3] + pm * tl.w + uf * fl.w;
                    *(float4*)&out[((size_t)b * LSEQ + r) * DHEAD + 4 * dg] = ov;
                }
            }
        }
    }
}

extern "C" void kernel_launch(void* const* d_in, const int* in_sizes, int n_in,
                              void* d_out, int out_size)
{
    (void)in_sizes; (void)n_in; (void)out_size;
    const float* Q   = (const float*)d_in[0];
    const float* K   = (const float*)d_in[1];
    const float* V   = (const float*)d_in[2];
    const int*   dur = (const int*)d_in[3];

    float* out   = (float*)d_out;
    float* score = out + (size_t)BATCH * LSEQ * DHEAD;   // tuple order: (out, score)

    vsum_kernel<<<BATCH, 256>>>(V, dur);

    const int smem_bytes = SMEM_FLOATS * (int)sizeof(float);   // 197,888 B
    cudaFuncSetAttribute(sdpa_fused_kernel,
                         cudaFuncAttributeMaxDynamicSharedMemorySize, smem_bytes);
    dim3 grid((LSEQ + TQ - 1) / TQ, BATCH);   // (29, 64)
    sdpa_fused_kernel<<<grid, NTHREADS, smem_bytes>>>(Q, K, V, dur, out, score);
}

// round 17
// speedup vs baseline: 1.1467x; 1.0090x over previous
#include <cuda_runtime.h>
#include <math_constants.h>
#include <cstdint>

#define BATCH 64
#define LSEQ  900
#define DHEAD 64
#define TQ    32          // query rows per CTA
#define TKB   256         // key cols per chunk (phase B)
#define TKC   128         // value cols per sub-chunk (phase C, double-buffered)
#define SPITCH 960        // padded score row pitch
#define QPITCH 36
#define NTHREADS 512

typedef unsigned long long ull;

// Per-batch V column sums (device-global scratch; no allocation).
__device__ __align__(16) float g_full[BATCH * DHEAD];
__device__ __align__(16) float g_tail[BATCH * DHEAD];

__device__ __forceinline__ void cp_async16(uint32_t dsm, const void* src, int szbytes) {
    asm volatile("cp.async.cg.shared.global [%0], [%1], 16, %2;\n"
                 :: "r"(dsm), "l"(src), "r"(szbytes));
}
__device__ __forceinline__ ull pack2(float a, float b) {
    ull r; asm("mov.b64 %0, {%1, %2};" : "=l"(r) : "f"(a), "f"(b)); return r;
}
__device__ __forceinline__ float2 unpack2(ull v) {
    float2 r; asm("mov.b64 {%0, %1}, %2;" : "=f"(r.x), "=f"(r.y) : "l"(v)); return r;
}
__device__ __forceinline__ ull fma2(ull a, ull b, ull c) {
    ull d; asm("fma.rn.f32x2 %0, %1, %2, %3;" : "=l"(d) : "l"(a), "l"(b), "l"(c)); return d;
}

// ---------------- kernel 1: per-batch full & tail V sums ----------------
__global__ void vsum_kernel(const float* __restrict__ V, const int* __restrict__ dur)
{
    __shared__ float sf[4][64];
    __shared__ float st_[4][64];
    const int b   = blockIdx.x;
    const int d   = threadIdx.x & 63;
    const int seg = threadIdx.x >> 6;
    const int durb = dur[b];
    const float* vb = V + (size_t)b * LSEQ * DHEAD;
    const int c0 = seg * 225, c1 = c0 + 225;
    float full = 0.f, tail = 0.f;
    for (int c = c0; c < c1; c++) {
        float v = vb[(size_t)c * DHEAD + d];
        full += v;
        if (c >= durb) tail += v;
    }
    sf[seg][d] = full;  st_[seg][d] = tail;
    __syncthreads();
    if (seg == 0) {
        g_full[b * 64 + d] = sf[0][d] + sf[1][d] + sf[2][d] + sf[3][d];
        g_tail[b * 64 + d] = st_[0][d] + st_[1][d] + st_[2][d] + st_[3][d];
    }
}

// ---------------- kernel 2: fused masked attention ----------------------
// SMEM floats: S 30720 | Qs 2304 (pitch 36, transposed) | Ks 16384 (K swizzled / 2x V halves / red) | pm 32 | uf 32
#define SMEM_FLOATS (TQ * SPITCH + 2304 + 16384 + 64)

__global__ __launch_bounds__(NTHREADS, 1)
void sdpa_fused_kernel(const float* __restrict__ Q,
                       const float* __restrict__ K,
                       const float* __restrict__ V,
                       const int*   __restrict__ dur,
                       float* __restrict__ out,
                       float* __restrict__ score)
{
    extern __shared__ float sm[];
    float* S   = sm;                       // [TQ][SPITCH]
    float* Qs  = sm + TQ * SPITCH;         // transposed Q: Qs[d*36 + qi]
    float* Ks  = Qs + 2304;                // swizzled transposed K / 2x V half-buffers
    float* pmv = Ks + 16384;               // per-row masked prob
    float* ufv = pmv + 32;                 // per-row uniform value

    const int tid  = threadIdx.x;
    const int b    = blockIdx.y;
    const int q0   = blockIdx.x * TQ;
    const int durb = dur[b];
    const int warp = tid >> 5;
    const int lane = tid & 31;
    const float inv900 = 1.0f / 900.0f;

    // ---- fast path: whole tile fully masked -> uniform rows --------------
    if (q0 >= durb) {
        const float4 u4 = make_float4(inv900, inv900, inv900, inv900);
        for (int qi = warp; qi < TQ; qi += 16) {
            int r = q0 + qi;
            if (r < LSEQ) {
                float* srow = score + ((size_t)b * LSEQ + r) * LSEQ;
                for (int g = lane; g < 225; g += 32)
                    __stcs((float4*)&srow[4 * g], u4);
            }
        }
        for (int e = tid; e < TQ * DHEAD; e += NTHREADS) {
            int qi = e >> 6, d = e & 63, r = q0 + qi;
            if (r < LSEQ)
                out[((size_t)b * LSEQ + r) * DHEAD + d] = g_full[b * 64 + d] * inv900;
        }
        return;
    }

    const int CP  = (durb + 63) & ~63;         // padded valid-col count (<=960)
    const int nch = (CP + TKB - 1) / TKB;

    const float* qb = Q + (size_t)b * LSEQ * DHEAD;
    const float* kb = K + (size_t)b * LSEQ * DHEAD;
    const float* vb = V + (size_t)b * LSEQ * DHEAD;

    // ---- Phase A: Q tile transposed into SMEM ----------------------------
    for (int e = tid; e < TQ * DHEAD; e += NTHREADS) {
        int qi = e >> 6, d = e & 63, r = q0 + qi;
        Qs[d * QPITCH + qi] = (r < durb) ? qb[(size_t)r * DHEAD + d] : 0.0f;
    }

    const int rowg = tid >> 7;    // 0..3   -> rows {8*rowg .. 8*rowg+7}
    const int colg = tid & 127;   // 0..127 -> cols {2*colg, 2*colg+1}

    // ---- Phase B: S = (Q K^T)/8 over valid columns only ------------------
    for (int ck = 0; ck < nch; ck++) {
        const int c0    = ck * TKB;
        const int width = min(TKB, CP - c0);
        __syncthreads();
        // K chunk -> swizzled transposed SMEM; LDGs batched in groups of 4 (MLP)
        #pragma unroll
        for (int grp = 0; grp < 2; grp++) {
            float4 stage[4];
            #pragma unroll
            for (int it = 0; it < 4; it++) {
                int vidx = tid + NTHREADS * (grp * 4 + it);
                int kj = vidx >> 4;
                int d4 = (vidx & 15) << 2;
                int c  = c0 + kj;
                stage[it] = make_float4(0.f, 0.f, 0.f, 0.f);
                if (kj < width && c < durb)
                    stage[it] = *(const float4*)&kb[(size_t)c * DHEAD + d4];
            }
            #pragma unroll
            for (int it = 0; it < 4; it++) {
                int vidx = tid + NTHREADS * (grp * 4 + it);
                int kj = vidx >> 4;
                int d4 = (vidx & 15) << 2;
                if (kj < width) {
                    const float* sp = (const float*)&stage[it];
                    #pragma unroll
                    for (int u = 0; u < 4; u++) {
                        int d = d4 + u;
                        int g = (kj >> 2) ^ ((d >> 2) & 15);
                        Ks[(d << 8) + (g << 2) + (kj & 3)] = sp[u];
                    }
                }
            }
        }
        __syncthreads();

        if (2 * colg < width) {
            ull a2[2][4];   // [col j][row pair p]; pair p = rows (2p, 2p+1) within 8-row group
            #pragma unroll
            for (int j = 0; j < 2; j++)
                #pragma unroll
                for (int p = 0; p < 4; p++) a2[j][p] = 0ull;

            const int ksub = (colg & 1) << 1;   // word offset within quad: 0 or 2
            const int kqd  = colg >> 1;         // quad index 0..63
            #pragma unroll 8
            for (int d = 0; d < DHEAD; d++) {
                ulonglong2 q01 = *(const ulonglong2*)&Qs[d * QPITCH + 8 * rowg];      // rows 0-3 of group
                ulonglong2 q23 = *(const ulonglong2*)&Qs[d * QPITCH + 8 * rowg + 4];  // rows 4-7
                int g = kqd ^ ((d >> 2) & 15);
                float2 kv = *(const float2*)&Ks[(d << 8) + (g << 2) + ksub];
                ull kx = pack2(kv.x, kv.x);
                ull ky = pack2(kv.y, kv.y);
                a2[0][0] = fma2(q01.x, kx, a2[0][0]);
                a2[0][1] = fma2(q01.y, kx, a2[0][1]);
                a2[0][2] = fma2(q23.x, kx, a2[0][2]);
                a2[0][3] = fma2(q23.y, kx, a2[0][3]);
                a2[1][0] = fma2(q01.x, ky, a2[1][0]);
                a2[1][1] = fma2(q01.y, ky, a2[1][1]);
                a2[1][2] = fma2(q23.x, ky, a2[1][2]);
                a2[1][3] = fma2(q23.y, ky, a2[1][3]);
            }

            const int cbase = c0 + 2 * colg;
            const float scl = 0.125f;
            const bool v0 = (cbase     < durb);
            const bool v1 = (cbase + 1 < durb);
            #pragma unroll
            for (int p = 0; p < 4; p++) {
                float2 c0v = unpack2(a2[0][p]);   // col cbase:   {row 2p, row 2p+1}
                float2 c1v = unpack2(a2[1][p]);   // col cbase+1
                float2 s0, s1;
                s0.x = v0 ? c0v.x * scl : -CUDART_INF_F;
                s0.y = v1 ? c1v.x * scl : -CUDART_INF_F;
                s1.x = v0 ? c0v.y * scl : -CUDART_INF_F;
                s1.y = v1 ? c1v.y * scl : -CUDART_INF_F;
                *(float2*)&S[(8 * rowg + 2 * p    ) * SPITCH + cbase] = s0;
                *(float2*)&S[(8 * rowg + 2 * p + 1) * SPITCH + cbase] = s1;
            }
        }
    }
    __syncthreads();

    // ---- Softmax per row (float4) + analytic masked tail + score write ---
    {
        const int NG = CP >> 2;          // float4 groups in valid region
        for (int qi = warp; qi < TQ; qi += 16) {
            const int r = q0 + qi;
            float* row = &S[qi * SPITCH];
            if (r < durb) {
                float m = -CUDART_INF_F;
                for (int g = lane; g < NG; g += 32) {
                    float4 v = *(const float4*)&row[4 * g];
                    m = fmaxf(m, fmaxf(fmaxf(v.x, v.y), fmaxf(v.z, v.w)));
                }
                #pragma unroll
                for (int o = 16; o; o >>= 1) m = fmaxf(m, __shfl_xor_sync(0xffffffffu, m, o));
                if (durb < LSEQ) m = fmaxf(m, -1e-12f);

                float ssum = 0.0f;
                for (int g = lane; g < NG; g += 32) {
                    float4 v = *(const float4*)&row[4 * g];
                    v.x = __expf(v.x - m);  v.y = __expf(v.y - m);
                    v.z = __expf(v.z - m);  v.w = __expf(v.w - m);
                    *(float4*)&row[4 * g] = v;
                    ssum += (v.x + v.y) + (v.z + v.w);
                }
                #pragma unroll
                for (int o = 16; o; o >>= 1) ssum += __shfl_xor_sync(0xffffffffu, ssum, o);

                float e_mask = (durb < LSEQ) ? __expf(-1e-12f - m) : 0.0f;
                float Z   = ssum + (float)(LSEQ - durb) * e_mask;
                float inv = 1.0f / Z;
                float pmask = e_mask * inv;
                if (lane == 0) { pmv[qi] = pmask; ufv[qi] = 0.0f; }

                float* srow = score + ((size_t)b * LSEQ + r) * LSEQ;
                for (int g = lane; g < 225; g += 32) {
                    int c = 4 * g;
                    float4 rv = *(const float4*)&row[c];   // garbage beyond CP, unused
                    float4 ov, wv;
                    float* rp = (float*)&rv; float* op = (float*)&ov; float* wp = (float*)&wv;
                    #pragma unroll
                    for (int u = 0; u < 4; u++) {
                        bool vld = (c + u) < durb;
                        float p = rp[u] * inv;
                        op[u] = vld ? p : pmask;
                        wp[u] = vld ? p : 0.0f;
                    }
                    if (c < CP) *(float4*)&row[c] = wv;
                    __stcs((float4*)&srow[c], ov);
                }
            } else {
                const float4 z4 = make_float4(0.f, 0.f, 0.f, 0.f);
                for (int g = lane; g < NG; g += 32) *(float4*)&row[4 * g] = z4;
                if (lane == 0) { pmv[qi] = 0.0f; ufv[qi] = inv900; }
                if (r < LSEQ) {
                    const float4 u4 = make_float4(inv900, inv900, inv900, inv900);
                    float* srow = score + ((size_t)b * LSEQ + r) * LSEQ;
                    for (int g = lane; g < 225; g += 32)
                        __stcs((float4*)&srow[4 * g], u4);
                }
            }
        }
    }
    __syncthreads();

    // ---- Phase C: out = P(valid) @ V, double-buffered cp.async V, FFMA2 --
    {
        const int qg2 = tid >> 6;        // 0..7  -> rows {4qg2..4qg2+3}
        const int dg  = tid & 15;        // 0..15 -> out cols {4dg..4dg+3}
        const int rep = (tid >> 4) & 3;  // split-K x4
        float* Vs = Ks;                  // two halves of 8192 floats each

        ull c2[4][2];
        #pragma unroll
        for (int i = 0; i < 4; i++) { c2[i][0] = 0ull; c2[i][1] = 0ull; }

        const int nck = (CP + TKC - 1) / TKC;   // 128-col sub-chunks (<=8)

        // prefetch sub-chunk 0 into half 0
        {
            const int clen0 = min(TKC, CP);
            #pragma unroll
            for (int it = 0; it < 4; it++) {
                int idx = tid + NTHREADS * it;
                int cc = idx >> 4, d4 = (idx & 15) << 2;
                if (cc < clen0) {
                    int c = cc;
                    uint32_t dsm = (uint32_t)__cvta_generic_to_shared(&Vs[cc * 64 + d4]);
                    const float* src = (c < durb) ? &vb[(size_t)c * DHEAD + d4] : vb;
                    cp_async16(dsm, src, (c < durb) ? 16 : 0);
                }
            }
            asm volatile("cp.async.commit_group;\n" ::: "memory");
        }

        for (int ci = 0; ci < nck; ci++) {
            const int buf0 = (ci & 1) * 8192;
            const int c0   = ci * TKC;
            const int clen = min(TKC, CP - c0);

            if (ci + 1 < nck) {
                const int c0n   = (ci + 1) * TKC;
                const int clen2 = min(TKC, CP - c0n);
                const int bufn  = ((ci + 1) & 1) * 8192;
                #pragma unroll
                for (int it = 0; it < 4; it++) {
                    int idx = tid + NTHREADS * it;
                    int cc = idx >> 4, d4 = (idx & 15) << 2;
                    if (cc < clen2) {
                        int c = c0n + cc;
                        uint32_t dsm = (uint32_t)__cvta_generic_to_shared(&Vs[bufn + cc * 64 + d4]);
                        const float* src = (c < durb) ? &vb[(size_t)c * DHEAD + d4] : vb;
                        cp_async16(dsm, src, (c < durb) ? 16 : 0);
                    }
                }
                asm volatile("cp.async.commit_group;\n" ::: "memory");
                asm volatile("cp.async.wait_group 1;\n" ::: "memory");
            } else {
                asm volatile("cp.async.wait_group 0;\n" ::: "memory");
            }
            __syncthreads();

            const int ngr = clen >> 2;
            #pragma unroll 2
            for (int ccg = rep; ccg < ngr; ccg += 4) {
                const int cb = c0 + 4 * ccg;
                float4 p[4];
                #pragma unroll
                for (int i = 0; i < 4; i++)
                    p[i] = *(const float4*)&S[(4 * qg2 + i) * SPITCH + cb];
                #pragma unroll
                for (int u = 0; u < 4; u++) {
                    ulonglong2 vv = *(const ulonglong2*)&Vs[buf0 + (4 * ccg + u) * 64 + 4 * dg];
                    #pragma unroll
                    for (int i = 0; i < 4; i++) {
                        float pu = ((const float*)&p[i])[u];
                        ull pu2 = pack2(pu, pu);
                        c2[i][0] = fma2(pu2, vv.x, c2[i][0]);
                        c2[i][1] = fma2(pu2, vv.y, c2[i][1]);
                    }
                }
            }
            __syncthreads();
        }

        // unpack packed accumulators
        float acc[4][4];
        #pragma unroll
        for (int i = 0; i < 4; i++) {
            float2 lo = unpack2(c2[i][0]);
            float2 hi = unpack2(c2[i][1]);
            acc[i][0] = lo.x; acc[i][1] = lo.y; acc[i][2] = hi.x; acc[i][3] = hi.y;
        }

        // split-K reduction in SMEM (reuse Qs/Ks region), padded stride 20
        float* red = Qs;
        const int cell = (qg2 * 16 + dg) * 20;
        if (rep) {
            #pragma unroll
            for (int i = 0; i < 4; i++)
                *(float4*)&red[(rep - 1) * 2560 + cell + 4 * i] =
                    make_float4(acc[i][0], acc[i][1], acc[i][2], acc[i][3]);
        }
        __syncthreads();
        if (rep == 0) {
            #pragma unroll
            for (int s = 0; s < 3; s++)
                #pragma unroll
                for (int i = 0; i < 4; i++) {
                    float4 rv = *(const float4*)&red[s * 2560 + cell + 4 * i];
                    acc[i][0] += rv.x;  acc[i][1] += rv.y;
                    acc[i][2] += rv.z;  acc[i][3] += rv.w;
                }
            float4 tl = *(const float4*)&g_tail[b * 64 + 4 * dg];
            float4 fl = *(const float4*)&g_full[b * 64 + 4 * dg];
            #pragma unroll
            for (int i = 0; i < 4; i++) {
                int qi = 4 * qg2 + i;
                int r  = q0 + qi;
                if (r < LSEQ) {
                    float pm = pmv[qi], uf = ufv[qi];
                    float4 ov;
                    ov.x = acc[i][0] + pm * tl.x + uf * fl.x;
                    ov.y = acc[i][1] + pm * tl.y + uf * fl.y;
                    ov.z = acc[i][2] + pm * tl.z + uf * fl.z;
                    ov.w = acc[i][3] + pm * tl.w + uf * fl.w;
                    *(float4*)&out[((size_t)b * LSEQ + r) * DHEAD + 4 * dg] = ov;
                }
            }
        }
    }
}

extern "C" void kernel_launch(void* const* d_in, const int* in_sizes, int n_in,
                              void* d_out, int out_size)
{
    (void)in_sizes; (void)n_in; (void)out_size;
    const float* Q   = (const float*)d_in[0];
    const float* K   = (const float*)d_in[1];
    const float* V   = (const float*)d_in[2];
    const int*   dur = (const int*)d_in[3];

    float* out   = (float*)d_out;
    float* score = out + (size_t)BATCH * LSEQ * DHEAD;   // tuple order: (out, score)

    vsum_kernel<<<BATCH, 256>>>(V, dur);

    const int smem_bytes = SMEM_FLOATS * (int)sizeof(float);   // 197,888 B
    cudaFuncSetAttribute(sdpa_fused_kernel,
                         cudaFuncAttributeMaxDynamicSharedMemorySize, smem_bytes);
    dim3 grid((LSEQ + TQ - 1) / TQ, BATCH);   // (29, 64)
    sdpa_fused_kernel<<<grid, NTHREADS, smem_bytes>>>(Q, K, V, dur, out, score);
}